// round 1
// baseline (speedup 1.0000x reference)
#include <cuda_runtime.h>
#include <cuda_bf16.h>
#include <math.h>

// Problem constants
#define MULT   16
#define IN_C   64
#define OUT_C  64
#define IN_S   56
#define OUT_S  52
#define KS     5

// Scratch: conv kernel, layout [kd][kh][i][oc][kw]  (5*5*64*64*5 floats = 2 MB)
__device__ float KG[KS * KS * IN_C * OUT_C * KS];

// ---------------------------------------------------------------------------
// Kernel builder: per tap, compute emb (radial basis), sh1 (angular), then the
// 64x64 channel-mixing matrix from weight. Skip connection (w_sc0/w_sc1 * 0.25)
// is folded into the center tap (2,2,2).
// ---------------------------------------------------------------------------
__global__ void build_kernel(const float* __restrict__ weight,
                             const float* __restrict__ w_sc0,
                             const float* __restrict__ w_sc1) {
    int tap = blockIdx.x;                 // 0..124
    int kd = tap / 25;
    int kh = (tap / 5) % 5;
    int kw = tap % 5;

    float rx = -1.f + 0.5f * (float)kd;
    float ry = -1.f + 0.5f * (float)kh;
    float rz = -1.f + 0.5f * (float)kw;
    float d = sqrtf(rx * rx + ry * ry + rz * rz);

    const float C = 1.14136f * 7.38905609893065f;  // 1.14136 * e^2
    float emb[5];
#pragma unroll
    for (int m = 0; m < 5; m++) {
        float diff = 4.f * d - (float)m;           // (d - m/4) / 0.25
        float t1 = diff + 1.f;
        float t2 = 1.f - diff;
        float s1 = (t1 > 0.f) ? expf(-1.f / t1) : 0.f;
        float s2 = (t2 > 0.f) ? expf(-1.f / t2) : 0.f;
        emb[m] = C * s1 * s2;
    }

    float dinv = 1.f / fmaxf(d, 1e-12f);
    const float SQ3 = 1.7320508075688772f;
    float sh1x = SQ3 * rx * dinv;
    float sh1y = SQ3 * ry * dinv;
    float sh1z = SQ3 * rz * dinv;
    float sh1[3] = { sh1x, sh1y, sh1z };

    const float PW0       = 0.1767766952966369f;   // sqrt(1/32); also = PW1/sqrt(3)
    const float INV_SQRT3 = 0.5773502691896258f;
    bool center = (kd == 2 && kh == 2 && kw == 2);

    for (int e = threadIdx.x; e < 64 * 64; e += blockDim.x) {
        int ic = e >> 6;
        int oc = e & 63;
        float val = 0.f;

        if (ic < MULT && oc < MULT) {
            // k_ss = PW0 * w1[u][w]
            int c = ic * 16 + oc;
            float wv = 0.f;
#pragma unroll
            for (int m = 0; m < 5; m++) wv += emb[m] * weight[m * 1024 + c];
            val = PW0 * wv;
            if (center) val += 0.25f * w_sc0[ic * 16 + oc];
        } else if (ic < MULT) {
            // k_sv: out col = 16 + 3w + k;  coeff PW1*INV_SQRT3 == PW0
            int o = oc - MULT;
            int w = o / 3;
            int k = o - 3 * w;
            int c = 256 + ic * 16 + w;
            float wv = 0.f;
#pragma unroll
            for (int m = 0; m < 5; m++) wv += emb[m] * weight[m * 1024 + c];
            val = PW0 * wv * sh1[k];
        } else if (oc < MULT) {
            // k_vs: in row = 16 + 3u + i;  coeff PW0*INV_SQRT3 (sh1 has the sqrt3)
            int iv = ic - MULT;
            int u = iv / 3;
            int i3 = iv - 3 * u;
            int c = 768 + u * 16 + oc;
            float wv = 0.f;
#pragma unroll
            for (int m = 0; m < 5; m++) wv += emb[m] * weight[m * 1024 + c];
            val = PW0 * INV_SQRT3 * wv * sh1[i3];
        } else {
            // k_vv: block diagonal in vector index; coeff PW1*INV_SQRT3 == PW0
            int iv = ic - MULT;
            int ov = oc - MULT;
            int u = iv / 3;
            int i3 = iv - 3 * u;
            int w = ov / 3;
            int j3 = ov - 3 * w;
            if (i3 == j3) {
                int c = 512 + u * 16 + w;
                float wv = 0.f;
#pragma unroll
                for (int m = 0; m < 5; m++) wv += emb[m] * weight[m * 1024 + c];
                val = PW0 * wv;
                if (center) val += 0.25f * w_sc1[u * 16 + w];
            }
        }
        KG[((( (kd * 5 + kh) * 64 + ic) * 64) + oc) * 5 + kw] = val;
    }
}

// ---------------------------------------------------------------------------
// Direct conv, fp32 FFMA. Block = (32 oc) x (52 ow) for one (od, oh).
// 128 threads: thread = (ocl = tid>>2 in 0..31, owg = tid&3 -> 13 outputs).
// Inner loop per input channel: 5 K coeffs + 17 x values -> 65 FFMA
// (FMA-pipe bound: 32.5 SM-cyc FFMA vs 22 cyc LDS per iteration).
// smem layouts chosen conflict-free: x addr stride 13 (4 distinct/warp,
// broadcast), K addr stride 5 over 8 distinct oc -> distinct banks.
// ---------------------------------------------------------------------------
__global__ void __launch_bounds__(128) conv_kernel(const float* __restrict__ x,
                                                   float* __restrict__ out) {
    __shared__ float xs[64 * 56];        // 14 KB  : xs[i][w]
    __shared__ float Ksm[32 * 32 * 5];   // 20 KB  : Ksm[il][ocl][kw]

    int ocg = blockIdx.x;    // 0..1
    int oh  = blockIdx.y;    // 0..51
    int od  = blockIdx.z;    // 0..51
    int tid = threadIdx.x;
    int ocl = tid >> 2;      // 0..31
    int owg = tid & 3;       // 0..3
    int ow0 = owg * 13;
    int oc0 = ocg * 32;

    float acc[13];
#pragma unroll
    for (int j = 0; j < 13; j++) acc[j] = 0.f;

    for (int kd = 0; kd < 5; kd++) {
        int dz = od + kd;
        for (int kh = 0; kh < 5; kh++) {
            int hy = oh + kh;
            __syncthreads();
            // Stage the 64 x 56 input slab for this (dz, hy)
            for (int idx = tid; idx < 64 * 56; idx += 128) {
                int i = idx / 56;
                int w = idx - i * 56;
                xs[idx] = x[((i * 56 + dz) * 56 + hy) * 56 + w];
            }
            const float* kg = &KG[(((kd * 5 + kh) * 64) * 64) * 5];

            for (int ih = 0; ih < 2; ih++) {
                // Stage K slice: i in [ih*32, ih*32+32), oc in [oc0, oc0+32)
                for (int idx = tid; idx < 32 * 32 * 5; idx += 128) {
                    int il   = idx / 160;
                    int rem  = idx - il * 160;
                    int ocl2 = rem / 5;
                    int kw2  = rem - ocl2 * 5;
                    Ksm[idx] = kg[((ih * 32 + il) * 64 + (oc0 + ocl2)) * 5 + kw2];
                }
                __syncthreads();

#pragma unroll 4
                for (int il = 0; il < 32; il++) {
                    const float* kp = &Ksm[il * 160 + ocl * 5];
                    float k0 = kp[0], k1 = kp[1], k2 = kp[2], k3 = kp[3], k4 = kp[4];
                    const float* xp = &xs[(ih * 32 + il) * 56 + ow0];
                    float xv[17];
#pragma unroll
                    for (int j = 0; j < 17; j++) xv[j] = xp[j];
#pragma unroll
                    for (int j = 0; j < 13; j++) {
                        acc[j] += k0 * xv[j];
                        acc[j] += k1 * xv[j + 1];
                        acc[j] += k2 * xv[j + 2];
                        acc[j] += k3 * xv[j + 3];
                        acc[j] += k4 * xv[j + 4];
                    }
                }
                __syncthreads();
            }
        }
    }

    int oc = oc0 + ocl;
    float* op = &out[((oc * 52 + od) * 52 + oh) * 52 + ow0];
#pragma unroll
    for (int j = 0; j < 13; j++) op[j] = acc[j];
}

// ---------------------------------------------------------------------------
extern "C" void kernel_launch(void* const* d_in, const int* in_sizes, int n_in,
                              void* d_out, int out_size) {
    const float* x      = (const float*)d_in[0];   // (1, 64, 56, 56, 56)
    const float* weight = (const float*)d_in[1];   // (5, 1024)
    const float* w_sc0  = (const float*)d_in[2];   // (16, 16)
    const float* w_sc1  = (const float*)d_in[3];   // (16, 16)
    float* out = (float*)d_out;                    // (1, 64, 52, 52, 52)

    build_kernel<<<125, 128>>>(weight, w_sc0, w_sc1);
    conv_kernel<<<dim3(2, 52, 52), 128>>>(x, out);
}

// round 2
// speedup vs baseline: 1.0015x; 1.0015x over previous
#include <cuda_runtime.h>
#include <cuda_bf16.h>
#include <math.h>

// Problem constants
#define MULT   16
#define IN_C   64
#define OUT_C  64
#define IN_S   56
#define OUT_S  52
#define KS     5

// Scratch: conv kernel, layout [kd][kh][i][oc][kw]  (5*5*64*64*5 floats = 2 MB)
__device__ float KG[KS * KS * IN_C * OUT_C * KS];

// ---------------------------------------------------------------------------
// Kernel builder: per tap, compute emb (radial basis), sh1 (angular), then the
// 64x64 channel-mixing matrix from weight. Skip connection (w_sc0/w_sc1 * 0.25)
// is folded into the center tap (2,2,2).
// ---------------------------------------------------------------------------
__global__ void build_kernel(const float* __restrict__ weight,
                             const float* __restrict__ w_sc0,
                             const float* __restrict__ w_sc1) {
    int tap = blockIdx.x;                 // 0..124
    int kd = tap / 25;
    int kh = (tap / 5) % 5;
    int kw = tap % 5;

    float rx = -1.f + 0.5f * (float)kd;
    float ry = -1.f + 0.5f * (float)kh;
    float rz = -1.f + 0.5f * (float)kw;
    float d = sqrtf(rx * rx + ry * ry + rz * rz);

    const float C = 1.14136f * 7.38905609893065f;  // 1.14136 * e^2
    float emb[5];
#pragma unroll
    for (int m = 0; m < 5; m++) {
        float diff = 4.f * d - (float)m;           // (d - m/4) / 0.25
        float t1 = diff + 1.f;
        float t2 = 1.f - diff;
        float s1 = (t1 > 0.f) ? expf(-1.f / t1) : 0.f;
        float s2 = (t2 > 0.f) ? expf(-1.f / t2) : 0.f;
        emb[m] = C * s1 * s2;
    }

    float dinv = 1.f / fmaxf(d, 1e-12f);
    const float SQ3 = 1.7320508075688772f;
    float sh1x = SQ3 * rx * dinv;
    float sh1y = SQ3 * ry * dinv;
    float sh1z = SQ3 * rz * dinv;
    float sh1[3] = { sh1x, sh1y, sh1z };

    const float PW0       = 0.1767766952966369f;   // sqrt(1/32); also = PW1/sqrt(3)
    const float INV_SQRT3 = 0.5773502691896258f;
    bool center = (kd == 2 && kh == 2 && kw == 2);

    for (int e = threadIdx.x; e < 64 * 64; e += blockDim.x) {
        int ic = e >> 6;
        int oc = e & 63;
        float val = 0.f;

        if (ic < MULT && oc < MULT) {
            // k_ss = PW0 * w1[u][w]
            int c = ic * 16 + oc;
            float wv = 0.f;
#pragma unroll
            for (int m = 0; m < 5; m++) wv += emb[m] * weight[m * 1024 + c];
            val = PW0 * wv;
            if (center) val += 0.25f * w_sc0[ic * 16 + oc];
        } else if (ic < MULT) {
            // k_sv: out col = 16 + 3w + k;  coeff PW1*INV_SQRT3 == PW0
            int o = oc - MULT;
            int w = o / 3;
            int k = o - 3 * w;
            int c = 256 + ic * 16 + w;
            float wv = 0.f;
#pragma unroll
            for (int m = 0; m < 5; m++) wv += emb[m] * weight[m * 1024 + c];
            val = PW0 * wv * sh1[k];
        } else if (oc < MULT) {
            // k_vs: in row = 16 + 3u + i;  coeff PW0*INV_SQRT3 (sh1 has the sqrt3)
            int iv = ic - MULT;
            int u = iv / 3;
            int i3 = iv - 3 * u;
            int c = 768 + u * 16 + oc;
            float wv = 0.f;
#pragma unroll
            for (int m = 0; m < 5; m++) wv += emb[m] * weight[m * 1024 + c];
            val = PW0 * INV_SQRT3 * wv * sh1[i3];
        } else {
            // k_vv: block diagonal in vector index; coeff PW1*INV_SQRT3 == PW0
            int iv = ic - MULT;
            int ov = oc - MULT;
            int u = iv / 3;
            int i3 = iv - 3 * u;
            int w = ov / 3;
            int j3 = ov - 3 * w;
            if (i3 == j3) {
                int c = 512 + u * 16 + w;
                float wv = 0.f;
#pragma unroll
                for (int m = 0; m < 5; m++) wv += emb[m] * weight[m * 1024 + c];
                val = PW0 * wv;
                if (center) val += 0.25f * w_sc1[u * 16 + w];
            }
        }
        KG[((( (kd * 5 + kh) * 64 + ic) * 64) + oc) * 5 + kw] = val;
    }
}

// ---------------------------------------------------------------------------
// Direct conv, fp32 FFMA. Block = (32 oc) x (52 ow) for one (od, oh).
// 128 threads: thread = (ocl = tid>>2 in 0..31, owg = tid&3 -> 13 outputs).
// Inner loop per input channel: 5 K coeffs + 17 x values -> 65 FFMA
// (FMA-pipe bound: 32.5 SM-cyc FFMA vs 22 cyc LDS per iteration).
// smem layouts chosen conflict-free: x addr stride 13 (4 distinct/warp,
// broadcast), K addr stride 5 over 8 distinct oc -> distinct banks.
// ---------------------------------------------------------------------------
__global__ void __launch_bounds__(128) conv_kernel(const float* __restrict__ x,
                                                   float* __restrict__ out) {
    __shared__ float xs[64 * 56];        // 14 KB  : xs[i][w]
    __shared__ float Ksm[32 * 32 * 5];   // 20 KB  : Ksm[il][ocl][kw]

    int ocg = blockIdx.x;    // 0..1
    int oh  = blockIdx.y;    // 0..51
    int od  = blockIdx.z;    // 0..51
    int tid = threadIdx.x;
    int ocl = tid >> 2;      // 0..31
    int owg = tid & 3;       // 0..3
    int ow0 = owg * 13;
    int oc0 = ocg * 32;

    float acc[13];
#pragma unroll
    for (int j = 0; j < 13; j++) acc[j] = 0.f;

    for (int kd = 0; kd < 5; kd++) {
        int dz = od + kd;
        for (int kh = 0; kh < 5; kh++) {
            int hy = oh + kh;
            __syncthreads();
            // Stage the 64 x 56 input slab for this (dz, hy)
            for (int idx = tid; idx < 64 * 56; idx += 128) {
                int i = idx / 56;
                int w = idx - i * 56;
                xs[idx] = x[((i * 56 + dz) * 56 + hy) * 56 + w];
            }
            const float* kg = &KG[(((kd * 5 + kh) * 64) * 64) * 5];

            for (int ih = 0; ih < 2; ih++) {
                // Stage K slice: i in [ih*32, ih*32+32), oc in [oc0, oc0+32)
                for (int idx = tid; idx < 32 * 32 * 5; idx += 128) {
                    int il   = idx / 160;
                    int rem  = idx - il * 160;
                    int ocl2 = rem / 5;
                    int kw2  = rem - ocl2 * 5;
                    Ksm[idx] = kg[((ih * 32 + il) * 64 + (oc0 + ocl2)) * 5 + kw2];
                }
                __syncthreads();

#pragma unroll 4
                for (int il = 0; il < 32; il++) {
                    const float* kp = &Ksm[il * 160 + ocl * 5];
                    float k0 = kp[0], k1 = kp[1], k2 = kp[2], k3 = kp[3], k4 = kp[4];
                    const float* xp = &xs[(ih * 32 + il) * 56 + ow0];
                    float xv[17];
#pragma unroll
                    for (int j = 0; j < 17; j++) xv[j] = xp[j];
#pragma unroll
                    for (int j = 0; j < 13; j++) {
                        acc[j] += k0 * xv[j];
                        acc[j] += k1 * xv[j + 1];
                        acc[j] += k2 * xv[j + 2];
                        acc[j] += k3 * xv[j + 3];
                        acc[j] += k4 * xv[j + 4];
                    }
                }
                __syncthreads();
            }
        }
    }

    int oc = oc0 + ocl;
    float* op = &out[((oc * 52 + od) * 52 + oh) * 52 + ow0];
#pragma unroll
    for (int j = 0; j < 13; j++) op[j] = acc[j];
}

// ---------------------------------------------------------------------------
extern "C" void kernel_launch(void* const* d_in, const int* in_sizes, int n_in,
                              void* d_out, int out_size) {
    const float* x      = (const float*)d_in[0];   // (1, 64, 56, 56, 56)
    const float* weight = (const float*)d_in[1];   // (5, 1024)
    const float* w_sc0  = (const float*)d_in[2];   // (16, 16)
    const float* w_sc1  = (const float*)d_in[3];   // (16, 16)
    float* out = (float*)d_out;                    // (1, 64, 52, 52, 52)

    build_kernel<<<125, 128>>>(weight, w_sc0, w_sc1);
    conv_kernel<<<dim3(2, 52, 52), 128>>>(x, out);
}

// round 8
// speedup vs baseline: 4.2325x; 4.2262x over previous
#include <cuda_runtime.h>
#include <cstdint>
#include <math.h>

// B in mma-fragment order: [tap 125][ks 8][nt 8][lane 32][rr 2] floats (16 KB/tap)
__device__ float BF[125 * 4096];
// x pre-converted to tf32 (rna), same layout as input x
__device__ float XT[64 * 56 * 56 * 56];

#define OS3 140608   // 52^3
#define OS2 2704     // 52^2

// ---------------------------------------------------------------------------
// Builder: 64x64 channel matrix per tap (skip folded into center tap 2,2,2),
// tf32-rounded, written in fragment order for m16n8k8.row.col tf32 mma:
//   B[k=ic][n=oc]: ks=ic>>3, rr=(ic&7)>>2, lane=(oc&7)*4+(ic&3), nt=oc>>3
// ---------------------------------------------------------------------------
__global__ void build_kernel(const float* __restrict__ weight,
                             const float* __restrict__ w_sc0,
                             const float* __restrict__ w_sc1) {
    int tap = blockIdx.x;
    int kd = tap / 25, kh = (tap / 5) % 5, kw = tap % 5;

    float rx = -1.f + 0.5f * kd, ry = -1.f + 0.5f * kh, rz = -1.f + 0.5f * kw;
    float d = sqrtf(rx * rx + ry * ry + rz * rz);
    const float C = 1.14136f * 7.38905609893065f;   // 1.14136 * e^2
    float emb[5];
#pragma unroll
    for (int m = 0; m < 5; m++) {
        float diff = 4.f * d - (float)m;
        float t1 = diff + 1.f, t2 = 1.f - diff;
        float s1 = (t1 > 0.f) ? expf(-1.f / t1) : 0.f;
        float s2 = (t2 > 0.f) ? expf(-1.f / t2) : 0.f;
        emb[m] = C * s1 * s2;
    }
    float dinv = 1.f / fmaxf(d, 1e-12f);
    const float SQ3 = 1.7320508075688772f;
    float sh1[3] = { SQ3 * rx * dinv, SQ3 * ry * dinv, SQ3 * rz * dinv };
    const float PW0 = 0.1767766952966369f, INV_SQRT3 = 0.5773502691896258f;
    bool center = (kd == 2 && kh == 2 && kw == 2);

    for (int e = threadIdx.x; e < 4096; e += blockDim.x) {
        int ic = e >> 6, oc = e & 63;
        float val = 0.f;
        if (ic < 16 && oc < 16) {
            int c = ic * 16 + oc; float wv = 0.f;
#pragma unroll
            for (int m = 0; m < 5; m++) wv += emb[m] * weight[m * 1024 + c];
            val = PW0 * wv;
            if (center) val += 0.25f * w_sc0[ic * 16 + oc];
        } else if (ic < 16) {
            int o = oc - 16, w2 = o / 3, k3 = o - 3 * w2;
            int c = 256 + ic * 16 + w2; float wv = 0.f;
#pragma unroll
            for (int m = 0; m < 5; m++) wv += emb[m] * weight[m * 1024 + c];
            val = PW0 * wv * sh1[k3];
        } else if (oc < 16) {
            int iv = ic - 16, u = iv / 3, i3 = iv - 3 * u;
            int c = 768 + u * 16 + oc; float wv = 0.f;
#pragma unroll
            for (int m = 0; m < 5; m++) wv += emb[m] * weight[m * 1024 + c];
            val = PW0 * INV_SQRT3 * wv * sh1[i3];
        } else {
            int iv = ic - 16, ov = oc - 16;
            int u = iv / 3, i3 = iv - 3 * u, w2 = ov / 3, j3 = ov - 3 * w2;
            if (i3 == j3) {
                int c = 512 + u * 16 + w2; float wv = 0.f;
#pragma unroll
                for (int m = 0; m < 5; m++) wv += emb[m] * weight[m * 1024 + c];
                val = PW0 * wv;
                if (center) val += 0.25f * w_sc1[u * 16 + w2];
            }
        }
        uint32_t v;
        asm("cvt.rna.tf32.f32 %0, %1;" : "=r"(v) : "f"(val));
        int ks = ic >> 3, k7 = ic & 7;
        int rr = k7 >> 2, lanei = (oc & 7) * 4 + (k7 & 3), nt = oc >> 3;
        ((uint32_t*)BF)[tap * 4096 + ((ks * 8 + nt) * 32 + lanei) * 2 + rr] = v;
    }
}

// Pre-convert x to tf32 (rna): 2809856 float4
__global__ void cvt_x_kernel(const float* __restrict__ x) {
    int i = blockIdx.x * 1024 + threadIdx.x;
    float4 v = ((const float4*)x)[i];
    uint4 o;
    asm("cvt.rna.tf32.f32 %0, %1;" : "=r"(o.x) : "f"(v.x));
    asm("cvt.rna.tf32.f32 %0, %1;" : "=r"(o.y) : "f"(v.y));
    asm("cvt.rna.tf32.f32 %0, %1;" : "=r"(o.z) : "f"(v.z));
    asm("cvt.rna.tf32.f32 %0, %1;" : "=r"(o.w) : "f"(v.w));
    ((uint4*)XT)[i] = o;
}

// ---------------------------------------------------------------------------
static __device__ __forceinline__ void cp16(uint32_t saddr, const float* g) {
    asm volatile("cp.async.cg.shared.global [%0], [%1], 16;"
                 :: "r"(saddr), "l"(g) : "memory");
}
static __device__ __forceinline__ void mma_tf32(float c[4], const uint32_t a[4],
                                                const uint32_t b[2]) {
    asm volatile("mma.sync.aligned.m16n8k8.row.col.f32.tf32.tf32.f32 "
                 "{%0,%1,%2,%3}, {%4,%5,%6,%7}, {%8,%9}, {%0,%1,%2,%3};"
                 : "+f"(c[0]), "+f"(c[1]), "+f"(c[2]), "+f"(c[3])
                 : "r"(a[0]), "r"(a[1]), "r"(a[2]), "r"(a[3]),
                   "r"(b[0]), "r"(b[1]));
}

// ---------------------------------------------------------------------------
// Conv: CTA = 4 output rows (row = od*52+oh). 128 threads; warp w owns row w:
// M=64 (ow 0..63, valid <52), N=64 oc, 128 accum regs/lane.
// smem: xs[4][ic 64][w 72] (73728 B) + B ring 2 x 16 KB = 106496 B.
// ---------------------------------------------------------------------------
__global__ void __launch_bounds__(128, 1) conv_kernel(float* __restrict__ out) {
    extern __shared__ float sm[];
    float* xs = sm;                 // 18432 floats
    float* Bs = sm + 18432;         // 8192 floats (2 slots)

    int tid = threadIdx.x, warp = tid >> 5, lane = tid & 31;
    int row0 = blockIdx.x * 4;
    int myrow = row0 + warp, myod = myrow / 52, myoh = myrow - myod * 52;

    uint32_t bs_u = (uint32_t)__cvta_generic_to_shared(Bs);

    // zero the w-pad region [56..72) once
    for (int i = tid; i < 4096; i += 128) {
        int r2 = i >> 10, rem = i & 1023, ic = rem >> 4, w = 56 + (rem & 15);
        xs[(r2 * 64 + ic) * 72 + w] = 0.f;
    }

    // prefetch B slices 0 and 1
    const float* bf = BF;
#pragma unroll 1
    for (int sl = 0; sl < 2; sl++) {
        for (int i = tid; i < 1024; i += 128)
            cp16(bs_u + sl * 16384 + i * 16, bf + sl * 4096 + i * 4);
        asm volatile("cp.async.commit_group;" ::: "memory");
    }

    float acc[4][8][4];
#pragma unroll
    for (int mt = 0; mt < 4; mt++)
#pragma unroll
        for (int nt = 0; nt < 8; nt++)
#pragma unroll
            for (int q = 0; q < 4; q++) acc[mt][nt][q] = 0.f;

    for (int g = 0; g < 25; g++) {
        int gd = g / 5, gh = g - gd * 5;
        __syncthreads();   // all warps done with previous xs
        for (int i = tid; i < 3584; i += 128) {
            int r2 = i / 896, rem = i - r2 * 896;
            int ic = rem / 14, wv = rem - ic * 14;
            int rowx = row0 + r2, odx = rowx / 52, ohx = rowx - odx * 52;
            float4 v = *(const float4*)&XT[ic * 175616 + (odx + gd) * 3136 +
                                           (ohx + gh) * 56 + wv * 4];
            *(float4*)&xs[(r2 * 64 + ic) * 72 + wv * 4] = v;
        }
        __syncthreads();

        for (int kw = 0; kw < 5; kw++) {
            int s = g * 5 + kw;
            asm volatile("cp.async.wait_group 1;" ::: "memory");
            __syncthreads();            // slice s visible to all warps

            const float* Bp = Bs + (s & 1) * 4096;
            const float* Ap = xs + warp * 4608 + (lane & 3) * 72 + (lane >> 2) + kw;

#pragma unroll
            for (int ks = 0; ks < 8; ks++) {
                uint32_t a[4][4];
#pragma unroll
                for (int mt = 0; mt < 4; mt++) {
                    const float* p = Ap + ks * 576 + mt * 16;
                    a[mt][0] = __float_as_uint(p[0]);
                    a[mt][1] = __float_as_uint(p[8]);
                    a[mt][2] = __float_as_uint(p[288]);
                    a[mt][3] = __float_as_uint(p[296]);
                }
                uint32_t b[8][2];
#pragma unroll
                for (int nt = 0; nt < 8; nt++) {
                    uint2 bb = *(const uint2*)&Bp[(ks * 8 + nt) * 64 + lane * 2];
                    b[nt][0] = bb.x; b[nt][1] = bb.y;
                }
#pragma unroll
                for (int mt = 0; mt < 4; mt++)
#pragma unroll
                    for (int nt = 0; nt < 8; nt++)
                        mma_tf32(acc[mt][nt], a[mt], b[nt]);
            }
            __syncthreads();            // all warps done with slice s (slot reuse)
            if (s + 2 < 125) {
                for (int i = tid; i < 1024; i += 128)
                    cp16(bs_u + ((s & 1) * 4096 + i * 4) * 4, bf + (s + 2) * 4096 + i * 4);
            }
            asm volatile("cp.async.commit_group;" ::: "memory");  // keep group count uniform
        }
    }

    // Epilogue: accum already holds out[ow][oc] for this row
    int base = myod * OS2 + myoh * 52;
#pragma unroll
    for (int mt = 0; mt < 4; mt++) {
        int ow = mt * 16 + (lane >> 2);
#pragma unroll
        for (int nt = 0; nt < 8; nt++) {
            int oc = nt * 8 + (lane & 3) * 2;
            if (ow < 52) {
                out[oc * OS3 + base + ow]       = acc[mt][nt][0];
                out[(oc + 1) * OS3 + base + ow] = acc[mt][nt][1];
            }
            if (ow + 8 < 52) {
                out[oc * OS3 + base + ow + 8]       = acc[mt][nt][2];
                out[(oc + 1) * OS3 + base + ow + 8] = acc[mt][nt][3];
            }
        }
    }
}

// ---------------------------------------------------------------------------
extern "C" void kernel_launch(void* const* d_in, const int* in_sizes, int n_in,
                              void* d_out, int out_size) {
    const float* x      = (const float*)d_in[0];   // (1, 64, 56, 56, 56)
    const float* weight = (const float*)d_in[1];   // (5, 1024)
    const float* w_sc0  = (const float*)d_in[2];   // (16, 16)
    const float* w_sc1  = (const float*)d_in[3];   // (16, 16)
    float* out = (float*)d_out;                    // (1, 64, 52, 52, 52)

    cudaFuncSetAttribute(conv_kernel, cudaFuncAttributeMaxDynamicSharedMemorySize, 106496);
    build_kernel<<<125, 128>>>(weight, w_sc0, w_sc1);
    cvt_x_kernel<<<2744, 1024>>>(x);
    conv_kernel<<<676, 128, 106496>>>(out);
}